// round 1
// baseline (speedup 1.0000x reference)
#include <cuda_runtime.h>
#include <math.h>

#define NB 65536
#define SLD 768   // state leading dimension: [x_embed(256) | z_h(256) | z_l(256)]

// ---------------- persistent device scratch (allocation-free rule) -----------
__device__ float g_S [(size_t)NB * SLD];   // state buffer
__device__ float g_Gi[(size_t)NB * 768];   // gate pre-activations (input path)
__device__ float g_Gh[(size_t)NB * 768];   // gate pre-activations (hidden path)
__device__ float g_Wp[768 * 512];          // high_w_ih with K-halves swapped

// ---------------- init: zero z_h, z_l columns --------------------------------
__global__ void zero_state_k() {
    long idx = (long)blockIdx.x * blockDim.x + threadIdx.x;   // NB*512 elems
    int b = (int)(idx >> 9);
    int c = (int)(idx & 511);
    g_S[(size_t)b * SLD + 256 + c] = 0.0f;
}

// swap the two 256-col halves of high_w_ih so that A = S+256 ([z_h | z_l])
// reproduces z_l @ Wl^T + z_h @ Wh^T
__global__ void permute_wih_k(const float* __restrict__ w) {
    int idx = blockIdx.x * blockDim.x + threadIdx.x;          // 768*512
    int r = idx >> 9, c = idx & 511;
    int sc = (c < 256) ? (c + 256) : (c - 256);
    g_Wp[r * 512 + c] = w[r * 512 + sc];
}

// ---------------- fp32 NT SGEMM: C[M,N] = A[M,K](lda) @ W[N,K]^T + bias ------
// tile 128x128x16, 256 threads, 8x8 per thread. All dims multiples of 128/16.
template<int ACT>   // 0 = none, 1 = exact GELU
__global__ __launch_bounds__(256) void sgemm_nt(
    const float* __restrict__ A, int lda,
    const float* __restrict__ W, int K,
    const float* __restrict__ bias,
    float* __restrict__ C, int ldc)
{
    __shared__ float As[16][128];
    __shared__ float Ws[16][128];

    const int m0 = blockIdx.y * 128;
    const int n0 = blockIdx.x * 128;
    const int tid = threadIdx.x;
    const int tx = tid & 15;       // 0..15 -> 8 output cols each
    const int ty = tid >> 4;       // 0..15 -> 8 output rows each

    float acc[8][8];
#pragma unroll
    for (int i = 0; i < 8; i++)
#pragma unroll
        for (int j = 0; j < 8; j++) acc[i][j] = 0.0f;

    for (int k0 = 0; k0 < K; k0 += 16) {
        // load A tile (128x16) and W tile (128x16), transposed into smem
#pragma unroll
        for (int l = 0; l < 2; l++) {
            int idx = tid + l * 256;           // 0..511 float4 slots
            int row = idx >> 2;                // 0..127
            int c4  = idx & 3;                 // 0..3 -> 4 floats
            float4 av = *(const float4*)(A + (size_t)(m0 + row) * lda + k0 + c4 * 4);
            As[c4 * 4 + 0][row] = av.x;
            As[c4 * 4 + 1][row] = av.y;
            As[c4 * 4 + 2][row] = av.z;
            As[c4 * 4 + 3][row] = av.w;
            float4 wv = *(const float4*)(W + (size_t)(n0 + row) * K + k0 + c4 * 4);
            Ws[c4 * 4 + 0][row] = wv.x;
            Ws[c4 * 4 + 1][row] = wv.y;
            Ws[c4 * 4 + 2][row] = wv.z;
            Ws[c4 * 4 + 3][row] = wv.w;
        }
        __syncthreads();

#pragma unroll
        for (int kk = 0; kk < 16; kk++) {
            float4 a0 = *(const float4*)&As[kk][ty * 8];
            float4 a1 = *(const float4*)&As[kk][ty * 8 + 4];
            float4 b0 = *(const float4*)&Ws[kk][tx * 8];
            float4 b1 = *(const float4*)&Ws[kk][tx * 8 + 4];
            float ar[8] = {a0.x, a0.y, a0.z, a0.w, a1.x, a1.y, a1.z, a1.w};
            float br[8] = {b0.x, b0.y, b0.z, b0.w, b1.x, b1.y, b1.z, b1.w};
#pragma unroll
            for (int i = 0; i < 8; i++)
#pragma unroll
                for (int j = 0; j < 8; j++)
                    acc[i][j] += ar[i] * br[j];
        }
        __syncthreads();
    }

    // epilogue: bias (+ GELU), vectorized store
    const int n = n0 + tx * 8;
    float bv[8];
#pragma unroll
    for (int j = 0; j < 8; j++) bv[j] = bias[n + j];

#pragma unroll
    for (int i = 0; i < 8; i++) {
        float v[8];
#pragma unroll
        for (int j = 0; j < 8; j++) {
            float t = acc[i][j] + bv[j];
            if (ACT == 1)
                t = 0.5f * t * (1.0f + erff(t * 0.70710678118654752f));
            v[j] = t;
        }
        float* cp = C + (size_t)(m0 + ty * 8 + i) * ldc + n;
        *(float4*)(cp)     = make_float4(v[0], v[1], v[2], v[3]);
        *(float4*)(cp + 4) = make_float4(v[4], v[5], v[6], v[7]);
    }
}

// ---------------- GRU gate fusion: h' = (1-z)*n + z*h ------------------------
// gi/gh are [B,768] (r,z,n blocks of 256); h points at the state column.
__global__ void gru_gate_k(const float* __restrict__ gi,
                           const float* __restrict__ gh,
                           float* __restrict__ h)
{
    int idx = blockIdx.x * blockDim.x + threadIdx.x;   // NB*256
    int b = idx >> 8;
    int j = idx & 255;
    size_t o = (size_t)b * 768;
    float r = 1.0f / (1.0f + expf(-(gi[o + j]       + gh[o + j])));
    float z = 1.0f / (1.0f + expf(-(gi[o + 256 + j] + gh[o + 256 + j])));
    float n = tanhf(gi[o + 512 + j] + r * gh[o + 512 + j]);
    float* hp = h + (size_t)b * SLD + j;
    float hv = *hp;
    *hp = (1.0f - z) * n + z * hv;
}

// ---------------- output head: LayerNorm + Linear(256->2) + state copies -----
__global__ void head_k(const float* __restrict__ ln_g, const float* __restrict__ ln_b,
                       const float* __restrict__ ow,  const float* __restrict__ ob,
                       float* __restrict__ out, int full)
{
    int warp = threadIdx.x >> 5;
    int lane = threadIdx.x & 31;
    int b = blockIdx.x * 8 + warp;

    const float* zh = g_S + (size_t)b * SLD + 256;
    float v[8];
    float s = 0.0f;
#pragma unroll
    for (int i = 0; i < 8; i++) { v[i] = zh[i * 32 + lane]; s += v[i]; }
#pragma unroll
    for (int o = 16; o; o >>= 1) s += __shfl_xor_sync(0xffffffffu, s, o);
    float mu = s * (1.0f / 256.0f);

    float q = 0.0f;
#pragma unroll
    for (int i = 0; i < 8; i++) { float d = v[i] - mu; q += d * d; }
#pragma unroll
    for (int o = 16; o; o >>= 1) q += __shfl_xor_sync(0xffffffffu, q, o);
    float rstd = rsqrtf(q * (1.0f / 256.0f) + 1e-5f);

    float d0 = 0.0f, d1 = 0.0f;
#pragma unroll
    for (int i = 0; i < 8; i++) {
        int j = i * 32 + lane;
        float nm = (v[i] - mu) * rstd * ln_g[j] + ln_b[j];
        d0 += nm * ow[j];
        d1 += nm * ow[256 + j];
    }
#pragma unroll
    for (int o = 16; o; o >>= 1) {
        d0 += __shfl_xor_sync(0xffffffffu, d0, o);
        d1 += __shfl_xor_sync(0xffffffffu, d1, o);
    }

    size_t lbase = full ? (size_t)NB * 512 : 0;
    if (lane == 0) {
        out[lbase + 2 * (size_t)b]     = d0 + ob[0];
        out[lbase + 2 * (size_t)b + 1] = d1 + ob[1];
    }
    if (full) {
        const float* zl = g_S + (size_t)b * SLD + 512;
#pragma unroll
        for (int i = 0; i < 8; i++) {
            int j = i * 32 + lane;
            out[(size_t)b * 256 + j]                    = v[i];     // z_h_new
            out[(size_t)NB * 256 + (size_t)b * 256 + j] = zl[j];    // z_l_new
        }
    }
}

// ---------------- launch ------------------------------------------------------
extern "C" void kernel_launch(void* const* d_in, const int* in_sizes, int n_in,
                              void* d_out, int out_size)
{
    const float* x         = (const float*)d_in[0];
    const float* proj_w    = (const float*)d_in[1];
    const float* proj_b    = (const float*)d_in[2];
    const float* low_w_ih  = (const float*)d_in[3];
    const float* low_w_hh  = (const float*)d_in[4];
    const float* low_b_ih  = (const float*)d_in[5];
    const float* low_b_hh  = (const float*)d_in[6];
    const float* high_w_ih = (const float*)d_in[7];
    const float* high_w_hh = (const float*)d_in[8];
    const float* high_b_ih = (const float*)d_in[9];
    const float* high_b_hh = (const float*)d_in[10];
    const float* ln_g      = (const float*)d_in[11];
    const float* ln_b      = (const float*)d_in[12];
    const float* out_w     = (const float*)d_in[13];
    const float* out_b     = (const float*)d_in[14];
    float* out = (float*)d_out;

    float *S, *Gi, *Gh, *Wp;
    cudaGetSymbolAddress((void**)&S,  g_S);
    cudaGetSymbolAddress((void**)&Gi, g_Gi);
    cudaGetSymbolAddress((void**)&Gh, g_Gh);
    cudaGetSymbolAddress((void**)&Wp, g_Wp);

    zero_state_k<<<(NB * 512) / 256, 256>>>();
    permute_wih_k<<<(768 * 512) / 256, 256>>>(high_w_ih);

    // x_embed = GELU(x @ proj_w^T + proj_b)  -> S cols [0,256)
    sgemm_nt<1><<<dim3(2, NB / 128), 256>>>(x, 512, proj_w, 512, proj_b, S, SLD);

    for (int i = 0; i < 12; i++) {
        // low GRU: gi over full state [x_embed|z_h|z_l] (K=768), gh over z_l (K=256)
        sgemm_nt<0><<<dim3(6, NB / 128), 256>>>(S,       SLD, low_w_ih, 768, low_b_ih, Gi, 768);
        sgemm_nt<0><<<dim3(6, NB / 128), 256>>>(S + 512, SLD, low_w_hh, 256, low_b_hh, Gh, 768);
        gru_gate_k<<<(NB * 256) / 256, 256>>>(Gi, Gh, S + 512);

        if ((i + 1) % 4 == 0) {
            // high GRU: input [z_l|z_h] via permuted weights over S cols [256,768)
            sgemm_nt<0><<<dim3(6, NB / 128), 256>>>(S + 256, SLD, Wp,        512, high_b_ih, Gi, 768);
            sgemm_nt<0><<<dim3(6, NB / 128), 256>>>(S + 256, SLD, high_w_hh, 256, high_b_hh, Gh, 768);
            gru_gate_k<<<(NB * 256) / 256, 256>>>(Gi, Gh, S + 256);
        }
    }

    int full = (out_size >= NB * 514) ? 1 : 0;
    head_k<<<NB / 8, 256>>>(ln_g, ln_b, out_w, out_b, out, full);
}

// round 3
// speedup vs baseline: 2.1367x; 2.1367x over previous
#include <cuda_runtime.h>
#include <cuda_bf16.h>
#include <math.h>
#include <stdint.h>

#define NB 65536

// ---------------- persistent device scratch (allocation-free rule) -----------
__device__ __align__(16) float g_S [(size_t)NB * 768];
__device__ __align__(16) float g_Gi[(size_t)NB * 768];
__device__ __align__(16) float g_Gh[(size_t)NB * 768];
__device__ __align__(16) __nv_bfloat16 g_Shi[(size_t)NB * 768];
__device__ __align__(16) __nv_bfloat16 g_Slo[(size_t)NB * 768];
__device__ __align__(16) __nv_bfloat16 g_Xhi[(size_t)NB * 512];
__device__ __align__(16) __nv_bfloat16 g_Xlo[(size_t)NB * 512];
__device__ __align__(16) __nv_bfloat16 g_LIh[768*768], g_LIl[768*768];
__device__ __align__(16) __nv_bfloat16 g_LHh[768*256], g_LHl[768*256];
__device__ __align__(16) __nv_bfloat16 g_HIh[768*512], g_HIl[768*512];
__device__ __align__(16) __nv_bfloat16 g_HHh[768*256], g_HHl[768*256];
__device__ __align__(16) __nv_bfloat16 g_PWh[256*512], g_PWl[256*512];

// ================= PTX helpers (sm_80-level features only) ====================
__device__ __forceinline__ uint32_t smem_u32(const void* p) {
    uint32_t a;
    asm("{ .reg .u64 t; cvta.to.shared.u64 t, %1; cvt.u32.u64 %0, t; }" : "=r"(a) : "l"(p));
    return a;
}
__device__ __forceinline__ void cpa16(uint32_t dst, const void* src) {
    asm volatile("cp.async.cg.shared.global [%0], [%1], 16;" :: "r"(dst), "l"(src));
}
__device__ __forceinline__ void cpa_commit() { asm volatile("cp.async.commit_group;" ::: "memory"); }
template<int N> __device__ __forceinline__ void cpa_wait() {
    asm volatile("cp.async.wait_group %0;" :: "n"(N) : "memory");
}
__device__ __forceinline__ void ldm4(uint32_t* r, uint32_t addr) {
    asm volatile("ldmatrix.sync.aligned.m8n8.x4.shared.b16 {%0,%1,%2,%3}, [%4];"
        : "=r"(r[0]), "=r"(r[1]), "=r"(r[2]), "=r"(r[3]) : "r"(addr));
}
__device__ __forceinline__ void mma16816(float* d, const uint32_t* a, uint32_t b0, uint32_t b1) {
    asm volatile("mma.sync.aligned.m16n8k16.row.col.f32.bf16.bf16.f32 "
        "{%0,%1,%2,%3},{%4,%5,%6,%7},{%8,%9},{%0,%1,%2,%3};"
        : "+f"(d[0]), "+f"(d[1]), "+f"(d[2]), "+f"(d[3])
        : "r"(a[0]), "r"(a[1]), "r"(a[2]), "r"(a[3]), "r"(b0), "r"(b1));
}

// ================= split-bf16 HMMA GEMM ======================================
// C[M, N] = A @ W^T + bias, A/W given as bf16 (hi, lo) pairs; fp32 acc.
// CTA tile 128(M) x 256(N) x 32(K), 8 warps (warp tile 64x64), 3 cp.async stages.
// smem row layout: 128B = [hi 32 bf16 | lo 32 bf16], chunk ^= (row & 7) swizzle.
#define STG_BYTES 49152u          // A 16KB + W 32KB per stage
#define SMEM_BYTES (3 * 49152)

__device__ __forceinline__ void load_stage(
    uint32_t sA, int tid,
    const __nv_bfloat16* __restrict__ Ah, const __nv_bfloat16* __restrict__ Al, int lda,
    const __nv_bfloat16* __restrict__ Wh, const __nv_bfloat16* __restrict__ Wl, int ldw,
    int m0, int n0, int kc)
{
    uint32_t sW = sA + 16384u;
#pragma unroll
    for (int i = 0; i < 4; i++) {                  // A: 128 rows x 8 x 16B
        int idx = tid + (i << 8);
        int row = idx >> 3, ch = idx & 7;
        uint32_t off = (uint32_t)(row * 128 + ((ch ^ (row & 7)) << 4));
        const __nv_bfloat16* src = (ch < 4)
            ? (Ah + (size_t)(m0 + row) * lda + kc + ch * 8)
            : (Al + (size_t)(m0 + row) * lda + kc + (ch - 4) * 8);
        cpa16(sA + off, src);
    }
#pragma unroll
    for (int i = 0; i < 8; i++) {                  // W: 256 rows x 8 x 16B
        int idx = tid + (i << 8);
        int row = idx >> 3, ch = idx & 7;
        uint32_t off = (uint32_t)(row * 128 + ((ch ^ (row & 7)) << 4));
        const __nv_bfloat16* src = (ch < 4)
            ? (Wh + (size_t)(n0 + row) * ldw + kc + ch * 8)
            : (Wl + (size_t)(n0 + row) * ldw + kc + (ch - 4) * 8);
        cpa16(sW + off, src);
    }
}

// MODE 0: C += bias (fp32 store). MODE 1: GELU -> Sout fp32 + Shi/Slo bf16.
template<int MODE>
__global__ __launch_bounds__(256, 1) void hmma_gemm(
    const __nv_bfloat16* __restrict__ Ah, const __nv_bfloat16* __restrict__ Al, int lda,
    const __nv_bfloat16* __restrict__ Wh, const __nv_bfloat16* __restrict__ Wl, int K,
    const float* __restrict__ bias,
    float* __restrict__ C, int ldc,
    float* __restrict__ Sout, __nv_bfloat16* __restrict__ Shi, __nv_bfloat16* __restrict__ Slo)
{
    extern __shared__ __align__(1024) char smem[];
    const uint32_t sb = smem_u32(smem);
    const int tid = threadIdx.x;
    const int m0 = blockIdx.y * 128;
    const int n0 = blockIdx.x * 256;
    const int nch = K >> 5;

    const int lane = tid & 31, warp = tid >> 5;
    const int wm = warp >> 2, wn = warp & 3;       // 2 x 4 warp grid
    const int lr = lane & 15, lkc = lane >> 4, sw = lane & 7;

    // per-thread ldmatrix base offsets (row part)
    const uint32_t a_row = (uint32_t)((wm * 64 + lr) * 128);
    const uint32_t b_row = (uint32_t)((wn * 64 + lr) * 128);

    float acc[4][8][4];
#pragma unroll
    for (int im = 0; im < 4; im++)
#pragma unroll
        for (int in = 0; in < 8; in++)
#pragma unroll
            for (int q = 0; q < 4; q++) acc[im][in][q] = 0.0f;

    // prologue: stages 0, 1
    load_stage(sb,             tid, Ah, Al, lda, Wh, Wl, K, m0, n0, 0);
    cpa_commit();
    load_stage(sb + STG_BYTES, tid, Ah, Al, lda, Wh, Wl, K, m0, n0, 32);
    cpa_commit();

    for (int c = 0; c < nch; c++) {
        cpa_wait<1>();
        __syncthreads();
        if (c + 2 < nch)
            load_stage(sb + (uint32_t)((c + 2) % 3) * STG_BYTES, tid,
                       Ah, Al, lda, Wh, Wl, K, m0, n0, (c + 2) << 5);
        cpa_commit();      // uniform group counting (empty groups at tail are fine)

        const uint32_t sA = sb + (uint32_t)(c % 3) * STG_BYTES;
        const uint32_t sW = sA + 16384u;

#pragma unroll
        for (int kk = 0; kk < 2; kk++) {
            const int chHi = (kk << 1) | lkc;      // hi chunks 0..3
            const int chLo = chHi + 4;             // lo chunks 4..7
            uint32_t Af[4][4], Bh[4][4], Bl[4][4];

#pragma unroll
            for (int im = 0; im < 4; im++)
                ldm4(Af[im], sA + a_row + im * 2048 + (uint32_t)((chHi ^ sw) << 4));
#pragma unroll
            for (int l = 0; l < 4; l++)
                ldm4(Bh[l], sW + b_row + l * 2048 + (uint32_t)((chHi ^ sw) << 4));
            // pass 1: Ahi * Whi
#pragma unroll
            for (int im = 0; im < 4; im++)
#pragma unroll
                for (int l = 0; l < 4; l++) {
                    mma16816(acc[im][2*l],   Af[im], Bh[l][0], Bh[l][2]);
                    mma16816(acc[im][2*l+1], Af[im], Bh[l][1], Bh[l][3]);
                }
            // pass 2: Ahi * Wlo
#pragma unroll
            for (int l = 0; l < 4; l++)
                ldm4(Bl[l], sW + b_row + l * 2048 + (uint32_t)((chLo ^ sw) << 4));
#pragma unroll
            for (int im = 0; im < 4; im++)
#pragma unroll
                for (int l = 0; l < 4; l++) {
                    mma16816(acc[im][2*l],   Af[im], Bl[l][0], Bl[l][2]);
                    mma16816(acc[im][2*l+1], Af[im], Bl[l][1], Bl[l][3]);
                }
            // pass 3: Alo * Whi (overwrite A frags)
#pragma unroll
            for (int im = 0; im < 4; im++)
                ldm4(Af[im], sA + a_row + im * 2048 + (uint32_t)((chLo ^ sw) << 4));
#pragma unroll
            for (int im = 0; im < 4; im++)
#pragma unroll
                for (int l = 0; l < 4; l++) {
                    mma16816(acc[im][2*l],   Af[im], Bh[l][0], Bh[l][2]);
                    mma16816(acc[im][2*l+1], Af[im], Bh[l][1], Bh[l][3]);
                }
        }
    }

    // epilogue
    const int r0 = lane >> 2;
    const int c2 = 2 * (lane & 3);
#pragma unroll
    for (int im = 0; im < 4; im++) {
#pragma unroll
        for (int in = 0; in < 8; in++) {
            const int gm = m0 + wm * 64 + im * 16 + r0;
            const int gn = n0 + wn * 64 + in * 8 + c2;
            const float b0 = bias[gn], b1 = bias[gn + 1];
#pragma unroll
            for (int h = 0; h < 2; h++) {          // rows gm, gm+8
                const int row = gm + h * 8;
                float v0 = acc[im][in][2*h]   + b0;
                float v1 = acc[im][in][2*h+1] + b1;
                if (MODE == 1) {
                    v0 = 0.5f * v0 * (1.0f + erff(v0 * 0.70710678118654752f));
                    v1 = 0.5f * v1 * (1.0f + erff(v1 * 0.70710678118654752f));
                    size_t o = (size_t)row * 768 + gn;
                    *(float2*)(Sout + o) = make_float2(v0, v1);
                    __nv_bfloat16 h0 = __float2bfloat16(v0);
                    __nv_bfloat16 h1 = __float2bfloat16(v1);
                    __nv_bfloat162 hp; hp.x = h0; hp.y = h1;
                    __nv_bfloat162 lp;
                    lp.x = __float2bfloat16(v0 - __bfloat162float(h0));
                    lp.y = __float2bfloat16(v1 - __bfloat162float(h1));
                    *(__nv_bfloat162*)(Shi + o) = hp;
                    *(__nv_bfloat162*)(Slo + o) = lp;
                } else {
                    *(float2*)(C + (size_t)row * ldc + gn) = make_float2(v0, v1);
                }
            }
        }
    }
}

// ---------------- small kernels ----------------------------------------------
__global__ void zero_state_k() {
    long idx = (long)blockIdx.x * blockDim.x + threadIdx.x;   // NB*512
    int b = (int)(idx >> 9);
    int c = (int)(idx & 511);
    size_t o = (size_t)b * 768 + 256 + c;
    g_S[o] = 0.0f;
    g_Shi[o] = __float2bfloat16(0.0f);
    g_Slo[o] = __float2bfloat16(0.0f);
}
__global__ void split_generic_k(const float* __restrict__ w,
                                __nv_bfloat16* __restrict__ hi,
                                __nv_bfloat16* __restrict__ lo, int n) {
    int i = blockIdx.x * 256 + threadIdx.x;
    if (i < n) {
        float v = w[i];
        __nv_bfloat16 h = __float2bfloat16(v);
        hi[i] = h;
        lo[i] = __float2bfloat16(v - __bfloat162float(h));
    }
}
__global__ void split_perm_k(const float* __restrict__ w) {   // high_w_ih col-swap
    int i = blockIdx.x * 256 + threadIdx.x;                    // 768*512
    int r = i >> 9, c = i & 511;
    int sc = (c < 256) ? (c + 256) : (c - 256);
    float v = w[r * 512 + sc];
    __nv_bfloat16 h = __float2bfloat16(v);
    g_HIh[r * 512 + c] = h;
    g_HIl[r * 512 + c] = __float2bfloat16(v - __bfloat162float(h));
}
__global__ void gru_gate_k(const float* __restrict__ gi, const float* __restrict__ gh,
                           int colbase) {
    int idx = blockIdx.x * blockDim.x + threadIdx.x;   // NB*256
    int b = idx >> 8;
    int j = idx & 255;
    size_t o = (size_t)b * 768;
    float r = 1.0f / (1.0f + expf(-(gi[o + j]       + gh[o + j])));
    float z = 1.0f / (1.0f + expf(-(gi[o + 256 + j] + gh[o + 256 + j])));
    float n = tanhf(gi[o + 512 + j] + r * gh[o + 512 + j]);
    size_t sc = o + colbase + j;
    float hv = g_S[sc];
    float hn = (1.0f - z) * n + z * hv;
    g_S[sc] = hn;
    __nv_bfloat16 h = __float2bfloat16(hn);
    g_Shi[sc] = h;
    g_Slo[sc] = __float2bfloat16(hn - __bfloat162float(h));
}
__global__ void head_k(const float* __restrict__ ln_g, const float* __restrict__ ln_b,
                       const float* __restrict__ ow,  const float* __restrict__ ob,
                       float* __restrict__ out, int full)
{
    int warp = threadIdx.x >> 5;
    int lane = threadIdx.x & 31;
    int b = blockIdx.x * 8 + warp;

    const float* zh = g_S + (size_t)b * 768 + 256;
    float v[8];
    float s = 0.0f;
#pragma unroll
    for (int i = 0; i < 8; i++) { v[i] = zh[i * 32 + lane]; s += v[i]; }
#pragma unroll
    for (int o = 16; o; o >>= 1) s += __shfl_xor_sync(0xffffffffu, s, o);
    float mu = s * (1.0f / 256.0f);
    float q = 0.0f;
#pragma unroll
    for (int i = 0; i < 8; i++) { float d = v[i] - mu; q += d * d; }
#pragma unroll
    for (int o = 16; o; o >>= 1) q += __shfl_xor_sync(0xffffffffu, q, o);
    float rstd = rsqrtf(q * (1.0f / 256.0f) + 1e-5f);
    float d0 = 0.0f, d1 = 0.0f;
#pragma unroll
    for (int i = 0; i < 8; i++) {
        int j = i * 32 + lane;
        float nm = (v[i] - mu) * rstd * ln_g[j] + ln_b[j];
        d0 += nm * ow[j];
        d1 += nm * ow[256 + j];
    }
#pragma unroll
    for (int o = 16; o; o >>= 1) {
        d0 += __shfl_xor_sync(0xffffffffu, d0, o);
        d1 += __shfl_xor_sync(0xffffffffu, d1, o);
    }
    size_t lbase = full ? (size_t)NB * 512 : 0;
    if (lane == 0) {
        out[lbase + 2 * (size_t)b]     = d0 + ob[0];
        out[lbase + 2 * (size_t)b + 1] = d1 + ob[1];
    }
    if (full) {
        const float* zl = g_S + (size_t)b * 768 + 512;
#pragma unroll
        for (int i = 0; i < 8; i++) {
            int j = i * 32 + lane;
            out[(size_t)b * 256 + j]                    = v[i];
            out[(size_t)NB * 256 + (size_t)b * 256 + j] = zl[j];
        }
    }
}

// ---------------- launch ------------------------------------------------------
extern "C" void kernel_launch(void* const* d_in, const int* in_sizes, int n_in,
                              void* d_out, int out_size)
{
    const float* x         = (const float*)d_in[0];
    const float* proj_w    = (const float*)d_in[1];
    const float* proj_b    = (const float*)d_in[2];
    const float* low_w_ih  = (const float*)d_in[3];
    const float* low_w_hh  = (const float*)d_in[4];
    const float* low_b_ih  = (const float*)d_in[5];
    const float* low_b_hh  = (const float*)d_in[6];
    const float* high_w_ih = (const float*)d_in[7];
    const float* high_w_hh = (const float*)d_in[8];
    const float* high_b_ih = (const float*)d_in[9];
    const float* high_b_hh = (const float*)d_in[10];
    const float* ln_g      = (const float*)d_in[11];
    const float* ln_b      = (const float*)d_in[12];
    const float* out_w     = (const float*)d_in[13];
    const float* out_b     = (const float*)d_in[14];
    float* out = (float*)d_out;

    float *S, *Gi, *Gh;
    __nv_bfloat16 *Shi, *Slo, *Xh, *Xl;
    __nv_bfloat16 *LIh, *LIl, *LHh, *LHl, *HIh, *HIl, *HHh, *HHl, *PWh, *PWl;
    cudaGetSymbolAddress((void**)&S,   g_S);
    cudaGetSymbolAddress((void**)&Gi,  g_Gi);
    cudaGetSymbolAddress((void**)&Gh,  g_Gh);
    cudaGetSymbolAddress((void**)&Shi, g_Shi);
    cudaGetSymbolAddress((void**)&Slo, g_Slo);
    cudaGetSymbolAddress((void**)&Xh,  g_Xhi);
    cudaGetSymbolAddress((void**)&Xl,  g_Xlo);
    cudaGetSymbolAddress((void**)&LIh, g_LIh);
    cudaGetSymbolAddress((void**)&LIl, g_LIl);
    cudaGetSymbolAddress((void**)&LHh, g_LHh);
    cudaGetSymbolAddress((void**)&LHl, g_LHl);
    cudaGetSymbolAddress((void**)&HIh, g_HIh);
    cudaGetSymbolAddress((void**)&HIl, g_HIl);
    cudaGetSymbolAddress((void**)&HHh, g_HHh);
    cudaGetSymbolAddress((void**)&HHl, g_HHl);
    cudaGetSymbolAddress((void**)&PWh, g_PWh);
    cudaGetSymbolAddress((void**)&PWl, g_PWl);

    cudaFuncSetAttribute(hmma_gemm<0>, cudaFuncAttributeMaxDynamicSharedMemorySize, SMEM_BYTES);
    cudaFuncSetAttribute(hmma_gemm<1>, cudaFuncAttributeMaxDynamicSharedMemorySize, SMEM_BYTES);

    // prep
    zero_state_k<<<(NB * 512) / 256, 256>>>();
    split_generic_k<<<(NB * 512 + 255) / 256, 256>>>(x, Xh, Xl, NB * 512);
    split_generic_k<<<(256 * 512 + 255) / 256, 256>>>(proj_w,    PWh, PWl, 256 * 512);
    split_generic_k<<<(768 * 768 + 255) / 256, 256>>>(low_w_ih,  LIh, LIl, 768 * 768);
    split_generic_k<<<(768 * 256 + 255) / 256, 256>>>(low_w_hh,  LHh, LHl, 768 * 256);
    split_generic_k<<<(768 * 256 + 255) / 256, 256>>>(high_w_hh, HHh, HHl, 768 * 256);
    split_perm_k   <<<(768 * 512) / 256, 256>>>(high_w_ih);

    // x_embed = GELU(x @ proj_w^T + b) -> S[:,0:256] (fp32 + bf16 hi/lo)
    hmma_gemm<1><<<dim3(1, NB / 128), 256, SMEM_BYTES>>>(
        Xh, Xl, 512, PWh, PWl, 512, proj_b, nullptr, 0, S, Shi, Slo);

    for (int i = 0; i < 12; i++) {
        hmma_gemm<0><<<dim3(3, NB / 128), 256, SMEM_BYTES>>>(
            Shi, Slo, 768, LIh, LIl, 768, low_b_ih, Gi, 768, nullptr, nullptr, nullptr);
        hmma_gemm<0><<<dim3(3, NB / 128), 256, SMEM_BYTES>>>(
            Shi + 512, Slo + 512, 768, LHh, LHl, 256, low_b_hh, Gh, 768, nullptr, nullptr, nullptr);
        gru_gate_k<<<(NB * 256) / 256, 256>>>(Gi, Gh, 512);

        if ((i + 1) % 4 == 0) {
            hmma_gemm<0><<<dim3(3, NB / 128), 256, SMEM_BYTES>>>(
                Shi + 256, Slo + 256, 768, HIh, HIl, 512, high_b_ih, Gi, 768, nullptr, nullptr, nullptr);
            hmma_gemm<0><<<dim3(3, NB / 128), 256, SMEM_BYTES>>>(
                Shi + 256, Slo + 256, 768, HHh, HHl, 256, high_b_hh, Gh, 768, nullptr, nullptr, nullptr);
            gru_gate_k<<<(NB * 256) / 256, 256>>>(Gi, Gh, 256);
        }
    }

    int full = (out_size >= NB * 514) ? 1 : 0;
    head_k<<<NB / 8, 256>>>(ln_g, ln_b, out_w, out_b, out, full);
}

// round 4
// speedup vs baseline: 2.1617x; 1.0117x over previous
#include <cuda_runtime.h>
#include <cuda_bf16.h>
#include <math.h>
#include <stdint.h>

#define NB 65536
typedef __nv_bfloat16 bf16;

// ---------------- persistent device scratch (allocation-free rule) -----------
// x split into two 256-col segments (row stride 256 each)
__device__ __align__(16) bf16 g_Xh[2][(size_t)NB*256], g_Xl[2][(size_t)NB*256];
__device__ __align__(16) bf16 g_XEh[(size_t)NB*256],   g_XEl[(size_t)NB*256];
__device__ __align__(16) bf16 g_ZHh[2][(size_t)NB*256], g_ZHl[2][(size_t)NB*256];
__device__ __align__(16) bf16 g_ZLh[2][(size_t)NB*256], g_ZLl[2][(size_t)NB*256];
// combined interleaved gate weights: rows 4j+{0:r,1:z,2:i_n,3:h_n}
__device__ __align__(16) bf16 g_WLh[1024*768], g_WLl[1024*768];
__device__ __align__(16) bf16 g_WHh[1024*512], g_WHl[1024*512];
__device__ __align__(16) bf16 g_PWh[256*512],  g_PWl[256*512];
__device__ __align__(16) float g_BL[1024], g_BH[1024];

// ================= PTX helpers (sm_80-level features only) ====================
__device__ __forceinline__ uint32_t smem_u32(const void* p) {
    uint32_t a;
    asm("{ .reg .u64 t; cvta.to.shared.u64 t, %1; cvt.u32.u64 %0, t; }" : "=r"(a) : "l"(p));
    return a;
}
__device__ __forceinline__ void cpa16(uint32_t dst, const void* src) {
    asm volatile("cp.async.cg.shared.global [%0], [%1], 16;" :: "r"(dst), "l"(src));
}
__device__ __forceinline__ void cpa_commit() { asm volatile("cp.async.commit_group;" ::: "memory"); }
template<int N> __device__ __forceinline__ void cpa_wait() {
    asm volatile("cp.async.wait_group %0;" :: "n"(N) : "memory");
}
__device__ __forceinline__ void ldm4(uint32_t* r, uint32_t addr) {
    asm volatile("ldmatrix.sync.aligned.m8n8.x4.shared.b16 {%0,%1,%2,%3}, [%4];"
        : "=r"(r[0]), "=r"(r[1]), "=r"(r[2]), "=r"(r[3]) : "r"(addr));
}
__device__ __forceinline__ void mma16816(float* d, const uint32_t* a, uint32_t b0, uint32_t b1) {
    asm volatile("mma.sync.aligned.m16n8k16.row.col.f32.bf16.bf16.f32 "
        "{%0,%1,%2,%3},{%4,%5,%6,%7},{%8,%9},{%0,%1,%2,%3};"
        : "+f"(d[0]), "+f"(d[1]), "+f"(d[2]), "+f"(d[3])
        : "r"(a[0]), "r"(a[1]), "r"(a[2]), "r"(a[3]), "r"(b0), "r"(b1));
}

// ================= fused split-bf16 HMMA GEMM =================================
// CTA tile 128(M) x 256(N) x 32(K), 8 warps (64x64), 4-stage cp.async.
// A given as up to 3 segments of NB x 256 (hi,lo); W row-major N x K (hi,lo).
// MODE 0: GRU gate epilogue (N interleaved [r,z,in,hn] per j), writes state hi/lo.
// MODE 1: GELU epilogue, writes hi/lo (x_embed).
#define STG_BYTES 49152u
#define SMEM_BYTES (4 * 49152)

__device__ __forceinline__ void load_stage(
    uint32_t sA, int tid,
    const bf16* __restrict__ Ah, const bf16* __restrict__ Al, int ca,
    const bf16* __restrict__ Wh, const bf16* __restrict__ Wl, int ldw,
    int m0, int n0, int kc)
{
    uint32_t sW = sA + 16384u;
#pragma unroll
    for (int i = 0; i < 4; i++) {                  // A: 128 rows x 8 x 16B
        int idx = tid + (i << 8);
        int row = idx >> 3, ch = idx & 7;
        uint32_t off = (uint32_t)(row * 128 + ((ch ^ (row & 7)) << 4));
        const bf16* src = (ch < 4)
            ? (Ah + (size_t)(m0 + row) * 256 + ca + ch * 8)
            : (Al + (size_t)(m0 + row) * 256 + ca + (ch - 4) * 8);
        cpa16(sA + off, src);
    }
#pragma unroll
    for (int i = 0; i < 8; i++) {                  // W: 256 rows x 8 x 16B
        int idx = tid + (i << 8);
        int row = idx >> 3, ch = idx & 7;
        uint32_t off = (uint32_t)(row * 128 + ((ch ^ (row & 7)) << 4));
        const bf16* src = (ch < 4)
            ? (Wh + (size_t)(n0 + row) * ldw + kc + ch * 8)
            : (Wl + (size_t)(n0 + row) * ldw + kc + (ch - 4) * 8);
        cpa16(sW + off, src);
    }
}

template<int MODE>
__global__ __launch_bounds__(256, 1) void gemm_fused(
    const bf16* __restrict__ A0h, const bf16* __restrict__ A1h, const bf16* __restrict__ A2h,
    const bf16* __restrict__ A0l, const bf16* __restrict__ A1l, const bf16* __restrict__ A2l,
    const bf16* __restrict__ Wh,  const bf16* __restrict__ Wl, int K,
    const float* __restrict__ bias,
    const bf16* __restrict__ Oldh, const bf16* __restrict__ Oldl,
    bf16* __restrict__ Outh, bf16* __restrict__ Outl)
{
    extern __shared__ __align__(1024) char smem[];
    const uint32_t sb = smem_u32(smem);
    const int tid = threadIdx.x;
    const int m0 = blockIdx.y * 128;
    const int n0 = blockIdx.x * 256;
    const int nch = K >> 5;

    const int lane = tid & 31, warp = tid >> 5;
    const int wm = warp >> 2, wn = warp & 3;
    const int lr = lane & 15, lkc = lane >> 4, sw = lane & 7;
    const uint32_t a_row = (uint32_t)((wm * 64 + lr) * 128);
    const uint32_t b_row = (uint32_t)((wn * 64 + lr) * 128);

    float acc[4][8][4];
#pragma unroll
    for (int im = 0; im < 4; im++)
#pragma unroll
        for (int in = 0; in < 8; in++)
#pragma unroll
            for (int q = 0; q < 4; q++) acc[im][in][q] = 0.0f;

    // prologue: 3 stages
#pragma unroll
    for (int p = 0; p < 3; p++) {
        int kc = p << 5;
        int s = kc >> 8;
        const bf16* ah = (s == 0) ? A0h : ((s == 1) ? A1h : A2h);
        const bf16* al = (s == 0) ? A0l : ((s == 1) ? A1l : A2l);
        load_stage(sb + (uint32_t)p * STG_BYTES, tid, ah, al, kc & 255, Wh, Wl, K, m0, n0, kc);
        cpa_commit();
    }

    for (int c = 0; c < nch; c++) {
        cpa_wait<2>();
        __syncthreads();
        if (c + 3 < nch) {
            int kc = (c + 3) << 5;
            int s = kc >> 8;
            const bf16* ah = (s == 0) ? A0h : ((s == 1) ? A1h : A2h);
            const bf16* al = (s == 0) ? A0l : ((s == 1) ? A1l : A2l);
            load_stage(sb + (uint32_t)((c + 3) & 3) * STG_BYTES, tid, ah, al, kc & 255,
                       Wh, Wl, K, m0, n0, kc);
        }
        cpa_commit();

        const uint32_t sA = sb + (uint32_t)(c & 3) * STG_BYTES;
        const uint32_t sW = sA + 16384u;

#pragma unroll
        for (int kk = 0; kk < 2; kk++) {
            const int chHi = (kk << 1) | lkc;
            const int chLo = chHi + 4;
            uint32_t Af[4][4], Bh[4][4], Bl[4][4];

#pragma unroll
            for (int im = 0; im < 4; im++)
                ldm4(Af[im], sA + a_row + im * 2048 + (uint32_t)((chHi ^ sw) << 4));
#pragma unroll
            for (int l = 0; l < 4; l++)
                ldm4(Bh[l], sW + b_row + l * 2048 + (uint32_t)((chHi ^ sw) << 4));
#pragma unroll
            for (int im = 0; im < 4; im++)
#pragma unroll
                for (int l = 0; l < 4; l++) {
                    mma16816(acc[im][2*l],   Af[im], Bh[l][0], Bh[l][2]);
                    mma16816(acc[im][2*l+1], Af[im], Bh[l][1], Bh[l][3]);
                }
#pragma unroll
            for (int l = 0; l < 4; l++)
                ldm4(Bl[l], sW + b_row + l * 2048 + (uint32_t)((chLo ^ sw) << 4));
#pragma unroll
            for (int im = 0; im < 4; im++)
#pragma unroll
                for (int l = 0; l < 4; l++) {
                    mma16816(acc[im][2*l],   Af[im], Bl[l][0], Bl[l][2]);
                    mma16816(acc[im][2*l+1], Af[im], Bl[l][1], Bl[l][3]);
                }
#pragma unroll
            for (int im = 0; im < 4; im++)
                ldm4(Af[im], sA + a_row + im * 2048 + (uint32_t)((chLo ^ sw) << 4));
#pragma unroll
            for (int im = 0; im < 4; im++)
#pragma unroll
                for (int l = 0; l < 4; l++) {
                    mma16816(acc[im][2*l],   Af[im], Bh[l][0], Bh[l][2]);
                    mma16816(acc[im][2*l+1], Af[im], Bh[l][1], Bh[l][3]);
                }
        }
    }

    const int r0 = lane >> 2, t = lane & 3;

    if (MODE == 0) {
        // GRU gate epilogue. Col layout per 8-col group: [r,z,in,hn] x 2 j's.
        const int jw = (n0 >> 2) + wn * 16;
        const bool act = ((t & 1) == 0);
#pragma unroll
        for (int im = 0; im < 4; im++) {
            const int row0 = m0 + wm * 64 + im * 16 + r0;
#pragma unroll
            for (int in = 0; in < 8; in++) {
                float a0 = acc[im][in][0], a1 = acc[im][in][1];
                float a2 = acc[im][in][2], a3 = acc[im][in][3];
                float p0 = __shfl_xor_sync(0xffffffffu, a0, 1);
                float p1 = __shfl_xor_sync(0xffffffffu, a1, 1);
                float p2 = __shfl_xor_sync(0xffffffffu, a2, 1);
                float p3 = __shfl_xor_sync(0xffffffffu, a3, 1);
                if (act) {
                    const int j = jw + in * 2 + (t >> 1);
                    const float4 bj = *(const float4*)(bias + 4 * j);
#pragma unroll
                    for (int h = 0; h < 2; h++) {
                        const int row = row0 + h * 8;
                        float rv = (h ? a2 : a0) + bj.x;
                        float zv = (h ? a3 : a1) + bj.y;
                        float iv = (h ? p2 : p0) + bj.z;
                        float hv = (h ? p3 : p1) + bj.w;
                        float r = 1.0f / (1.0f + expf(-rv));
                        float z = 1.0f / (1.0f + expf(-zv));
                        float n = tanhf(iv + r * hv);
                        size_t o = (size_t)row * 256 + j;
                        float hold = __bfloat162float(Oldh[o]) + __bfloat162float(Oldl[o]);
                        float hn = (1.0f - z) * n + z * hold;
                        bf16 hb = __float2bfloat16(hn);
                        Outh[o] = hb;
                        Outl[o] = __float2bfloat16(hn - __bfloat162float(hb));
                    }
                }
            }
        }
    } else {
        // GELU epilogue -> hi/lo bf16 (N == 256, n0 == 0)
        const int c2 = 2 * t;
#pragma unroll
        for (int im = 0; im < 4; im++) {
#pragma unroll
            for (int in = 0; in < 8; in++) {
                const int gn = wn * 64 + in * 8 + c2;
                const float b0 = bias[gn], b1 = bias[gn + 1];
#pragma unroll
                for (int h = 0; h < 2; h++) {
                    const int row = m0 + wm * 64 + im * 16 + r0 + h * 8;
                    float v0 = acc[im][in][2*h]   + b0;
                    float v1 = acc[im][in][2*h+1] + b1;
                    v0 = 0.5f * v0 * (1.0f + erff(v0 * 0.70710678118654752f));
                    v1 = 0.5f * v1 * (1.0f + erff(v1 * 0.70710678118654752f));
                    size_t o = (size_t)row * 256 + gn;
                    bf16 h0 = __float2bfloat16(v0);
                    bf16 h1 = __float2bfloat16(v1);
                    __nv_bfloat162 hp; hp.x = h0; hp.y = h1;
                    __nv_bfloat162 lp;
                    lp.x = __float2bfloat16(v0 - __bfloat162float(h0));
                    lp.y = __float2bfloat16(v1 - __bfloat162float(h1));
                    *(__nv_bfloat162*)(Outh + o) = hp;
                    *(__nv_bfloat162*)(Outl + o) = lp;
                }
            }
        }
    }
}

// ---------------- prep kernels -------------------------------------------------
__global__ void zero_state_k() {
    size_t i = (size_t)blockIdx.x * blockDim.x + threadIdx.x;   // NB*256
    bf16 z = __float2bfloat16(0.0f);
    g_ZHh[0][i] = z; g_ZHl[0][i] = z;
    g_ZLh[0][i] = z; g_ZLl[0][i] = z;
}
__global__ void split_x_k(const float* __restrict__ x) {
    size_t i = (size_t)blockIdx.x * blockDim.x + threadIdx.x;   // NB*512
    int b = (int)(i >> 9), c = (int)(i & 511);
    float v = x[i];
    bf16 h = __float2bfloat16(v);
    size_t o = (size_t)b * 256 + (c & 255);
    g_Xh[c >> 8][o] = h;
    g_Xl[c >> 8][o] = __float2bfloat16(v - __bfloat162float(h));
}
__global__ void split_generic_k(const float* __restrict__ w,
                                bf16* __restrict__ hi, bf16* __restrict__ lo, int n) {
    int i = blockIdx.x * 256 + threadIdx.x;
    if (i < n) {
        float v = w[i];
        bf16 h = __float2bfloat16(v);
        hi[i] = h;
        lo[i] = __float2bfloat16(v - __bfloat162float(h));
    }
}
// low combined: K=768, hh folds into cols [512,768)
__global__ void prep_low_w(const float* __restrict__ wi, const float* __restrict__ wh) {
    int i = blockIdx.x * 256 + threadIdx.x;   // 1024*768
    int r = i / 768, c = i % 768;
    int j = r >> 2, comp = r & 3;
    float v;
    if (comp == 0)      { v = wi[j * 768 + c];         if (c >= 512) v += wh[j * 256 + c - 512]; }
    else if (comp == 1) { v = wi[(256 + j) * 768 + c]; if (c >= 512) v += wh[(256 + j) * 256 + c - 512]; }
    else if (comp == 2) { v = wi[(512 + j) * 768 + c]; }
    else                { v = (c >= 512) ? wh[(512 + j) * 256 + c - 512] : 0.0f; }
    bf16 h = __float2bfloat16(v);
    g_WLh[i] = h;
    g_WLl[i] = __float2bfloat16(v - __bfloat162float(h));
}
// high combined: K=512 over [z_l | z_h], hh folds into cols [256,512)
__global__ void prep_high_w(const float* __restrict__ wi, const float* __restrict__ wh) {
    int i = blockIdx.x * 256 + threadIdx.x;   // 1024*512
    int r = i / 512, c = i % 512;
    int j = r >> 2, comp = r & 3;
    float v;
    if (comp == 0)      { v = wi[j * 512 + c];         if (c >= 256) v += wh[j * 256 + c - 256]; }
    else if (comp == 1) { v = wi[(256 + j) * 512 + c]; if (c >= 256) v += wh[(256 + j) * 256 + c - 256]; }
    else if (comp == 2) { v = wi[(512 + j) * 512 + c]; }
    else                { v = (c >= 256) ? wh[(512 + j) * 256 + c - 256] : 0.0f; }
    bf16 h = __float2bfloat16(v);
    g_WHh[i] = h;
    g_WHl[i] = __float2bfloat16(v - __bfloat162float(h));
}
__global__ void prep_bias_k(const float* __restrict__ bi, const float* __restrict__ bh,
                            float* __restrict__ bc) {
    int i = blockIdx.x * 256 + threadIdx.x;   // 1024
    if (i >= 1024) return;
    int j = i >> 2, comp = i & 3;
    float v;
    if (comp == 0)      v = bi[j] + bh[j];
    else if (comp == 1) v = bi[256 + j] + bh[256 + j];
    else if (comp == 2) v = bi[512 + j];
    else                v = bh[512 + j];
    bc[i] = v;
}

// ---------------- output head ---------------------------------------------------
__global__ void head_k(const bf16* __restrict__ zhh, const bf16* __restrict__ zhl,
                       const bf16* __restrict__ zlh, const bf16* __restrict__ zll,
                       const float* __restrict__ ln_g, const float* __restrict__ ln_b,
                       const float* __restrict__ ow,  const float* __restrict__ ob,
                       float* __restrict__ out, int full)
{
    int warp = threadIdx.x >> 5;
    int lane = threadIdx.x & 31;
    int b = blockIdx.x * 8 + warp;

    float v[8];
    float s = 0.0f;
#pragma unroll
    for (int i = 0; i < 8; i++) {
        size_t o = (size_t)b * 256 + i * 32 + lane;
        v[i] = __bfloat162float(zhh[o]) + __bfloat162float(zhl[o]);
        s += v[i];
    }
#pragma unroll
    for (int o = 16; o; o >>= 1) s += __shfl_xor_sync(0xffffffffu, s, o);
    float mu = s * (1.0f / 256.0f);
    float q = 0.0f;
#pragma unroll
    for (int i = 0; i < 8; i++) { float d = v[i] - mu; q += d * d; }
#pragma unroll
    for (int o = 16; o; o >>= 1) q += __shfl_xor_sync(0xffffffffu, q, o);
    float rstd = rsqrtf(q * (1.0f / 256.0f) + 1e-5f);
    float d0 = 0.0f, d1 = 0.0f;
#pragma unroll
    for (int i = 0; i < 8; i++) {
        int j = i * 32 + lane;
        float nm = (v[i] - mu) * rstd * ln_g[j] + ln_b[j];
        d0 += nm * ow[j];
        d1 += nm * ow[256 + j];
    }
#pragma unroll
    for (int o = 16; o; o >>= 1) {
        d0 += __shfl_xor_sync(0xffffffffu, d0, o);
        d1 += __shfl_xor_sync(0xffffffffu, d1, o);
    }
    size_t lbase = full ? (size_t)NB * 512 : 0;
    if (lane == 0) {
        out[lbase + 2 * (size_t)b]     = d0 + ob[0];
        out[lbase + 2 * (size_t)b + 1] = d1 + ob[1];
    }
    if (full) {
#pragma unroll
        for (int i = 0; i < 8; i++) {
            int j = i * 32 + lane;
            size_t o = (size_t)b * 256 + j;
            out[o] = v[i];
            out[(size_t)NB * 256 + o] = __bfloat162float(zlh[o]) + __bfloat162float(zll[o]);
        }
    }
}

// ---------------- launch ---------------------------------------------------------
extern "C" void kernel_launch(void* const* d_in, const int* in_sizes, int n_in,
                              void* d_out, int out_size)
{
    const float* x         = (const float*)d_in[0];
    const float* proj_w    = (const float*)d_in[1];
    const float* proj_b    = (const float*)d_in[2];
    const float* low_w_ih  = (const float*)d_in[3];
    const float* low_w_hh  = (const float*)d_in[4];
    const float* low_b_ih  = (const float*)d_in[5];
    const float* low_b_hh  = (const float*)d_in[6];
    const float* high_w_ih = (const float*)d_in[7];
    const float* high_w_hh = (const float*)d_in[8];
    const float* high_b_ih = (const float*)d_in[9];
    const float* high_b_hh = (const float*)d_in[10];
    const float* ln_g      = (const float*)d_in[11];
    const float* ln_b      = (const float*)d_in[12];
    const float* out_w     = (const float*)d_in[13];
    const float* out_b     = (const float*)d_in[14];
    float* out = (float*)d_out;

    bf16 *Xh0, *Xh1, *Xl0, *Xl1, *XEh, *XEl;
    bf16 *ZHh[2], *ZHl[2], *ZLh[2], *ZLl[2];
    bf16 *WLh, *WLl, *WHh, *WHl, *PWh, *PWl;
    float *BL, *BH;
    {
        bf16 *p;
        cudaGetSymbolAddress((void**)&p, g_Xh);  Xh0 = p; Xh1 = p + (size_t)NB*256;
        cudaGetSymbolAddress((void**)&p, g_Xl);  Xl0 = p; Xl1 = p + (size_t)NB*256;
        cudaGetSymbolAddress((void**)&XEh, g_XEh);
        cudaGetSymbolAddress((void**)&XEl, g_XEl);
        cudaGetSymbolAddress((void**)&p, g_ZHh); ZHh[0] = p; ZHh[1] = p + (size_t)NB*256;
        cudaGetSymbolAddress((void**)&p, g_ZHl); ZHl[0] = p; ZHl[1] = p + (size_t)NB*256;
        cudaGetSymbolAddress((void**)&p, g_ZLh); ZLh[0] = p; ZLh[1] = p + (size_t)NB*256;
        cudaGetSymbolAddress((void**)&p, g_ZLl); ZLl[0] = p; ZLl[1] = p + (size_t)NB*256;
        cudaGetSymbolAddress((void**)&WLh, g_WLh);
        cudaGetSymbolAddress((void**)&WLl, g_WLl);
        cudaGetSymbolAddress((void**)&WHh, g_WHh);
        cudaGetSymbolAddress((void**)&WHl, g_WHl);
        cudaGetSymbolAddress((void**)&PWh, g_PWh);
        cudaGetSymbolAddress((void**)&PWl, g_PWl);
        cudaGetSymbolAddress((void**)&BL, g_BL);
        cudaGetSymbolAddress((void**)&BH, g_BH);
    }

    cudaFuncSetAttribute(gemm_fused<0>, cudaFuncAttributeMaxDynamicSharedMemorySize, SMEM_BYTES);
    cudaFuncSetAttribute(gemm_fused<1>, cudaFuncAttributeMaxDynamicSharedMemorySize, SMEM_BYTES);

    // prep
    zero_state_k<<<(NB * 256) / 256, 256>>>();
    split_x_k<<<(NB * 512) / 256, 256>>>(x);
    split_generic_k<<<(256 * 512 + 255) / 256, 256>>>(proj_w, PWh, PWl, 256 * 512);
    prep_low_w <<<(1024 * 768) / 256, 256>>>(low_w_ih, low_w_hh);
    prep_high_w<<<(1024 * 512) / 256, 256>>>(high_w_ih, high_w_hh);
    prep_bias_k<<<4, 256>>>(low_b_ih,  low_b_hh,  BL);
    prep_bias_k<<<4, 256>>>(high_b_ih, high_b_hh, BH);

    // x_embed = GELU(x @ proj_w^T + b) -> XE hi/lo
    gemm_fused<1><<<dim3(1, NB / 128), 256, SMEM_BYTES>>>(
        Xh0, Xh1, Xh1, Xl0, Xl1, Xl1, PWh, PWl, 512, proj_b,
        nullptr, nullptr, XEh, XEl);

    int zh = 0, zl = 0;
    for (int i = 0; i < 12; i++) {
        // fused low GRU step: one GEMM, gate in epilogue
        gemm_fused<0><<<dim3(4, NB / 128), 256, SMEM_BYTES>>>(
            XEh, ZHh[zh], ZLh[zl], XEl, ZHl[zh], ZLl[zl],
            WLh, WLl, 768, BL,
            ZLh[zl], ZLl[zl], ZLh[zl ^ 1], ZLl[zl ^ 1]);
        zl ^= 1;

        if ((i + 1) % 4 == 0) {
            gemm_fused<0><<<dim3(4, NB / 128), 256, SMEM_BYTES>>>(
                ZLh[zl], ZHh[zh], ZHh[zh], ZLl[zl], ZHl[zh], ZHl[zh],
                WHh, WHl, 512, BH,
                ZHh[zh], ZHl[zh], ZHh[zh ^ 1], ZHl[zh ^ 1]);
            zh ^= 1;
        }
    }

    int full = (out_size >= NB * 514) ? 1 : 0;
    head_k<<<NB / 8, 256>>>(ZHh[zh], ZHl[zh], ZLh[zl], ZLl[zl],
                            ln_g, ln_b, out_w, out_b, out, full);
}

// round 5
// speedup vs baseline: 2.7597x; 1.2767x over previous
#include <cuda_runtime.h>
#include <cuda_bf16.h>
#include <math.h>
#include <stdint.h>

#define NB 65536
typedef __nv_bfloat16 bf16;

// ---------------- persistent device scratch (allocation-free rule) -----------
__device__ __align__(16) bf16 g_Xh[2][(size_t)NB*256], g_Xl[2][(size_t)NB*256];
__device__ __align__(16) bf16 g_XEh[(size_t)NB*256],   g_XEl[(size_t)NB*256];
__device__ __align__(16) bf16 g_ZHh[2][(size_t)NB*256], g_ZHl[2][(size_t)NB*256];
__device__ __align__(16) bf16 g_ZLh[2][(size_t)NB*256], g_ZLl[2][(size_t)NB*256];
// combined interleaved gate weights: rows 4j+{0:r,1:z,2:i_n,3:h_n}
__device__ __align__(16) bf16 g_WLh[1024*768], g_WLl[1024*768];
__device__ __align__(16) bf16 g_WHh[1024*512], g_WHl[1024*512];
__device__ __align__(16) bf16 g_PWh[256*512],  g_PWl[256*512];
__device__ __align__(16) float g_BL[1024], g_BH[1024];
// cached K-slices of the low-GRU pre-activation
__device__ __align__(16) float g_CX [(size_t)NB*1024];   // x_embed part + BL
__device__ __align__(16) float g_CXH[(size_t)NB*1024];   // CX + z_h part

// ================= PTX helpers (sm_80-level features only) ====================
__device__ __forceinline__ uint32_t smem_u32(const void* p) {
    uint32_t a;
    asm("{ .reg .u64 t; cvta.to.shared.u64 t, %1; cvt.u32.u64 %0, t; }" : "=r"(a) : "l"(p));
    return a;
}
__device__ __forceinline__ void cpa16(uint32_t dst, const void* src) {
    asm volatile("cp.async.cg.shared.global [%0], [%1], 16;" :: "r"(dst), "l"(src));
}
__device__ __forceinline__ void cpa_commit() { asm volatile("cp.async.commit_group;" ::: "memory"); }
template<int N> __device__ __forceinline__ void cpa_wait() {
    asm volatile("cp.async.wait_group %0;" :: "n"(N) : "memory");
}
__device__ __forceinline__ void ldm4(uint32_t* r, uint32_t addr) {
    asm volatile("ldmatrix.sync.aligned.m8n8.x4.shared.b16 {%0,%1,%2,%3}, [%4];"
        : "=r"(r[0]), "=r"(r[1]), "=r"(r[2]), "=r"(r[3]) : "r"(addr));
}
__device__ __forceinline__ void mma16816(float* d, const uint32_t* a, uint32_t b0, uint32_t b1) {
    asm volatile("mma.sync.aligned.m16n8k16.row.col.f32.bf16.bf16.f32 "
        "{%0,%1,%2,%3},{%4,%5,%6,%7},{%8,%9},{%0,%1,%2,%3};"
        : "+f"(d[0]), "+f"(d[1]), "+f"(d[2]), "+f"(d[3])
        : "r"(a[0]), "r"(a[1]), "r"(a[2]), "r"(a[3]), "r"(b0), "r"(b1));
}

// ================= fused split-bf16 HMMA GEMM =================================
// CTA tile 128(M) x 256(N) x 32(K), 8 warps (64x64), 4-stage cp.async.
// A: up to 2 segments of NB x 256 (hi,lo). W: row-major, ld=ldw, K-slice [0,K).
// MODE 0: GRU gate epilogue; pre = acc + (baseIn ? baseIn[row][4j+c] : bias[4j+c]).
// MODE 1: GELU -> hi/lo (x_embed).
// MODE 2: fp32 out = acc + bias.
// MODE 3: fp32 out = acc + baseIn[row][col].
#define STG_BYTES 49152u
#define SMEM_BYTES (4 * 49152)

__device__ __forceinline__ void load_stage(
    uint32_t sA, int tid,
    const bf16* __restrict__ A0h, const bf16* __restrict__ A1h,
    const bf16* __restrict__ A0l, const bf16* __restrict__ A1l,
    const bf16* __restrict__ Wh, const bf16* __restrict__ Wl, int ldw,
    int m0, int n0, int kc)
{
    const bf16* Ah = (kc < 256) ? A0h : A1h;
    const bf16* Al = (kc < 256) ? A0l : A1l;
    const int ca = kc & 255;
    uint32_t sW = sA + 16384u;
#pragma unroll
    for (int i = 0; i < 4; i++) {                  // A: 128 rows x 8 x 16B
        int idx = tid + (i << 8);
        int row = idx >> 3, ch = idx & 7;
        uint32_t off = (uint32_t)(row * 128 + ((ch ^ (row & 7)) << 4));
        const bf16* src = (ch < 4)
            ? (Ah + (size_t)(m0 + row) * 256 + ca + ch * 8)
            : (Al + (size_t)(m0 + row) * 256 + ca + (ch - 4) * 8);
        cpa16(sA + off, src);
    }
#pragma unroll
    for (int i = 0; i < 8; i++) {                  // W: 256 rows x 8 x 16B
        int idx = tid + (i << 8);
        int row = idx >> 3, ch = idx & 7;
        uint32_t off = (uint32_t)(row * 128 + ((ch ^ (row & 7)) << 4));
        const bf16* src = (ch < 4)
            ? (Wh + (size_t)(n0 + row) * ldw + kc + ch * 8)
            : (Wl + (size_t)(n0 + row) * ldw + kc + (ch - 4) * 8);
        cpa16(sW + off, src);
    }
}

template<int MODE>
__global__ __launch_bounds__(256, 1) void gemm_fused(
    const bf16* __restrict__ A0h, const bf16* __restrict__ A1h,
    const bf16* __restrict__ A0l, const bf16* __restrict__ A1l,
    const bf16* __restrict__ Wh,  const bf16* __restrict__ Wl, int ldw, int K,
    const float* __restrict__ bias, const float* __restrict__ baseIn,
    const bf16* __restrict__ Oldh, const bf16* __restrict__ Oldl,
    bf16* __restrict__ Outh, bf16* __restrict__ Outl, float* __restrict__ Cout)
{
    extern __shared__ __align__(1024) char smem[];
    const uint32_t sb = smem_u32(smem);
    const int tid = threadIdx.x;
    const int m0 = blockIdx.y * 128;
    const int n0 = blockIdx.x * 256;
    const int nch = K >> 5;

    const int lane = tid & 31, warp = tid >> 5;
    const int wm = warp >> 2, wn = warp & 3;
    const int lr = lane & 15, lkc = lane >> 4, sw = lane & 7;
    const uint32_t a_row = (uint32_t)((wm * 64 + lr) * 128);
    const uint32_t b_row = (uint32_t)((wn * 64 + lr) * 128);

    float acc[4][8][4];
#pragma unroll
    for (int im = 0; im < 4; im++)
#pragma unroll
        for (int in = 0; in < 8; in++)
#pragma unroll
            for (int q = 0; q < 4; q++) acc[im][in][q] = 0.0f;

    // prologue: 3 stages
#pragma unroll
    for (int p = 0; p < 3; p++) {
        load_stage(sb + (uint32_t)p * STG_BYTES, tid, A0h, A1h, A0l, A1l,
                   Wh, Wl, ldw, m0, n0, p << 5);
        cpa_commit();
    }

    for (int c = 0; c < nch; c++) {
        cpa_wait<2>();
        __syncthreads();
        if (c + 3 < nch)
            load_stage(sb + (uint32_t)((c + 3) & 3) * STG_BYTES, tid, A0h, A1h, A0l, A1l,
                       Wh, Wl, ldw, m0, n0, (c + 3) << 5);
        cpa_commit();

        const uint32_t sA = sb + (uint32_t)(c & 3) * STG_BYTES;
        const uint32_t sW = sA + 16384u;

#pragma unroll
        for (int kk = 0; kk < 2; kk++) {
            const int chHi = (kk << 1) | lkc;
            const int chLo = chHi + 4;
            uint32_t Af[4][4], Bh[4][4], Bl[4][4];

#pragma unroll
            for (int im = 0; im < 4; im++)
                ldm4(Af[im], sA + a_row + im * 2048 + (uint32_t)((chHi ^ sw) << 4));
#pragma unroll
            for (int l = 0; l < 4; l++)
                ldm4(Bh[l], sW + b_row + l * 2048 + (uint32_t)((chHi ^ sw) << 4));
#pragma unroll
            for (int im = 0; im < 4; im++)
#pragma unroll
                for (int l = 0; l < 4; l++) {
                    mma16816(acc[im][2*l],   Af[im], Bh[l][0], Bh[l][2]);
                    mma16816(acc[im][2*l+1], Af[im], Bh[l][1], Bh[l][3]);
                }
#pragma unroll
            for (int l = 0; l < 4; l++)
                ldm4(Bl[l], sW + b_row + l * 2048 + (uint32_t)((chLo ^ sw) << 4));
#pragma unroll
            for (int im = 0; im < 4; im++)
#pragma unroll
                for (int l = 0; l < 4; l++) {
                    mma16816(acc[im][2*l],   Af[im], Bl[l][0], Bl[l][2]);
                    mma16816(acc[im][2*l+1], Af[im], Bl[l][1], Bl[l][3]);
                }
#pragma unroll
            for (int im = 0; im < 4; im++)
                ldm4(Af[im], sA + a_row + im * 2048 + (uint32_t)((chLo ^ sw) << 4));
#pragma unroll
            for (int im = 0; im < 4; im++)
#pragma unroll
                for (int l = 0; l < 4; l++) {
                    mma16816(acc[im][2*l],   Af[im], Bh[l][0], Bh[l][2]);
                    mma16816(acc[im][2*l+1], Af[im], Bh[l][1], Bh[l][3]);
                }
        }
    }

    const int r0 = lane >> 2, t = lane & 3;

    if (MODE == 0) {
        // GRU gate epilogue. Col layout per 8-col group: [r,z,in,hn] x 2 j's.
        const int jw = (n0 >> 2) + wn * 16;
        const bool act = ((t & 1) == 0);
#pragma unroll
        for (int im = 0; im < 4; im++) {
            const int row0 = m0 + wm * 64 + im * 16 + r0;
#pragma unroll
            for (int in = 0; in < 8; in++) {
                float a0 = acc[im][in][0], a1 = acc[im][in][1];
                float a2 = acc[im][in][2], a3 = acc[im][in][3];
                float p0 = __shfl_xor_sync(0xffffffffu, a0, 1);
                float p1 = __shfl_xor_sync(0xffffffffu, a1, 1);
                float p2 = __shfl_xor_sync(0xffffffffu, a2, 1);
                float p3 = __shfl_xor_sync(0xffffffffu, a3, 1);
                if (act) {
                    const int j = jw + in * 2 + (t >> 1);
#pragma unroll
                    for (int h = 0; h < 2; h++) {
                        const int row = row0 + h * 8;
                        float4 bj = baseIn
                            ? *(const float4*)(baseIn + (size_t)row * 1024 + 4 * j)
                            : *(const float4*)(bias + 4 * j);
                        float rv = (h ? a2 : a0) + bj.x;
                        float zv = (h ? a3 : a1) + bj.y;
                        float iv = (h ? p2 : p0) + bj.z;
                        float hv = (h ? p3 : p1) + bj.w;
                        float r = 1.0f / (1.0f + expf(-rv));
                        float z = 1.0f / (1.0f + expf(-zv));
                        float n = tanhf(iv + r * hv);
                        size_t o = (size_t)row * 256 + j;
                        float hold = __bfloat162float(Oldh[o]) + __bfloat162float(Oldl[o]);
                        float hn = (1.0f - z) * n + z * hold;
                        bf16 hb = __float2bfloat16(hn);
                        Outh[o] = hb;
                        Outl[o] = __float2bfloat16(hn - __bfloat162float(hb));
                    }
                }
            }
        }
    } else if (MODE == 1) {
        // GELU epilogue -> hi/lo bf16 (N == 256, n0 == 0)
        const int c2 = 2 * t;
#pragma unroll
        for (int im = 0; im < 4; im++) {
#pragma unroll
            for (int in = 0; in < 8; in++) {
                const int gn = wn * 64 + in * 8 + c2;
                const float b0 = bias[gn], b1 = bias[gn + 1];
#pragma unroll
                for (int h = 0; h < 2; h++) {
                    const int row = m0 + wm * 64 + im * 16 + r0 + h * 8;
                    float v0 = acc[im][in][2*h]   + b0;
                    float v1 = acc[im][in][2*h+1] + b1;
                    v0 = 0.5f * v0 * (1.0f + erff(v0 * 0.70710678118654752f));
                    v1 = 0.5f * v1 * (1.0f + erff(v1 * 0.70710678118654752f));
                    size_t o = (size_t)row * 256 + gn;
                    bf16 h0 = __float2bfloat16(v0);
                    bf16 h1 = __float2bfloat16(v1);
                    __nv_bfloat162 hp; hp.x = h0; hp.y = h1;
                    __nv_bfloat162 lp;
                    lp.x = __float2bfloat16(v0 - __bfloat162float(h0));
                    lp.y = __float2bfloat16(v1 - __bfloat162float(h1));
                    *(__nv_bfloat162*)(Outh + o) = hp;
                    *(__nv_bfloat162*)(Outl + o) = lp;
                }
            }
        }
    } else {
        // MODE 2/3: fp32 out = acc + (bias | baseIn)
        const int c2 = 2 * t;
#pragma unroll
        for (int im = 0; im < 4; im++) {
#pragma unroll
            for (int in = 0; in < 8; in++) {
                const int gn = n0 + wn * 64 + in * 8 + c2;
#pragma unroll
                for (int h = 0; h < 2; h++) {
                    const int row = m0 + wm * 64 + im * 16 + r0 + h * 8;
                    float v0 = acc[im][in][2*h];
                    float v1 = acc[im][in][2*h+1];
                    if (MODE == 2) { v0 += bias[gn]; v1 += bias[gn + 1]; }
                    else {
                        float2 b = *(const float2*)(baseIn + (size_t)row * 1024 + gn);
                        v0 += b.x; v1 += b.y;
                    }
                    *(float2*)(Cout + (size_t)row * 1024 + gn) = make_float2(v0, v1);
                }
            }
        }
    }
}

// ---------------- prep kernels -------------------------------------------------
__global__ void zero_state_k() {
    size_t i = (size_t)blockIdx.x * blockDim.x + threadIdx.x;   // NB*256
    bf16 z = __float2bfloat16(0.0f);
    g_ZHh[0][i] = z; g_ZHl[0][i] = z;
    g_ZLh[0][i] = z; g_ZLl[0][i] = z;
}
__global__ void split_x_k(const float* __restrict__ x) {
    size_t i = (size_t)blockIdx.x * blockDim.x + threadIdx.x;   // NB*512
    int b = (int)(i >> 9), c = (int)(i & 511);
    float v = x[i];
    bf16 h = __float2bfloat16(v);
    size_t o = (size_t)b * 256 + (c & 255);
    g_Xh[c >> 8][o] = h;
    g_Xl[c >> 8][o] = __float2bfloat16(v - __bfloat162float(h));
}
__global__ void split_generic_k(const float* __restrict__ w,
                                bf16* __restrict__ hi, bf16* __restrict__ lo, int n) {
    int i = blockIdx.x * 256 + threadIdx.x;
    if (i < n) {
        float v = w[i];
        bf16 h = __float2bfloat16(v);
        hi[i] = h;
        lo[i] = __float2bfloat16(v - __bfloat162float(h));
    }
}
// low combined: K=768 over [x_embed|z_h|z_l], hh folds into cols [512,768)
__global__ void prep_low_w(const float* __restrict__ wi, const float* __restrict__ wh) {
    int i = blockIdx.x * 256 + threadIdx.x;   // 1024*768
    int r = i / 768, c = i % 768;
    int j = r >> 2, comp = r & 3;
    float v;
    if (comp == 0)      { v = wi[j * 768 + c];         if (c >= 512) v += wh[j * 256 + c - 512]; }
    else if (comp == 1) { v = wi[(256 + j) * 768 + c]; if (c >= 512) v += wh[(256 + j) * 256 + c - 512]; }
    else if (comp == 2) { v = wi[(512 + j) * 768 + c]; }
    else                { v = (c >= 512) ? wh[(512 + j) * 256 + c - 512] : 0.0f; }
    bf16 h = __float2bfloat16(v);
    g_WLh[i] = h;
    g_WLl[i] = __float2bfloat16(v - __bfloat162float(h));
}
// high combined: K=512 over [z_l | z_h], hh folds into cols [256,512)
__global__ void prep_high_w(const float* __restrict__ wi, const float* __restrict__ wh) {
    int i = blockIdx.x * 256 + threadIdx.x;   // 1024*512
    int r = i / 512, c = i % 512;
    int j = r >> 2, comp = r & 3;
    float v;
    if (comp == 0)      { v = wi[j * 512 + c];         if (c >= 256) v += wh[j * 256 + c - 256]; }
    else if (comp == 1) { v = wi[(256 + j) * 512 + c]; if (c >= 256) v += wh[(256 + j) * 256 + c - 256]; }
    else if (comp == 2) { v = wi[(512 + j) * 512 + c]; }
    else                { v = (c >= 256) ? wh[(512 + j) * 256 + c - 256] : 0.0f; }
    bf16 h = __float2bfloat16(v);
    g_WHh[i] = h;
    g_WHl[i] = __float2bfloat16(v - __bfloat162float(h));
}
__global__ void prep_bias_k(const float* __restrict__ bi, const float* __restrict__ bh,
                            float* __restrict__ bc) {
    int i = blockIdx.x * 256 + threadIdx.x;   // 1024
    if (i >= 1024) return;
    int j = i >> 2, comp = i & 3;
    float v;
    if (comp == 0)      v = bi[j] + bh[j];
    else if (comp == 1) v = bi[256 + j] + bh[256 + j];
    else if (comp == 2) v = bi[512 + j];
    else                v = bh[512 + j];
    bc[i] = v;
}

// ---------------- output head ---------------------------------------------------
__global__ void head_k(const bf16* __restrict__ zhh, const bf16* __restrict__ zhl,
                       const bf16* __restrict__ zlh, const bf16* __restrict__ zll,
                       const float* __restrict__ ln_g, const float* __restrict__ ln_b,
                       const float* __restrict__ ow,  const float* __restrict__ ob,
                       float* __restrict__ out, int full)
{
    int warp = threadIdx.x >> 5;
    int lane = threadIdx.x & 31;
    int b = blockIdx.x * 8 + warp;

    float v[8];
    float s = 0.0f;
#pragma unroll
    for (int i = 0; i < 8; i++) {
        size_t o = (size_t)b * 256 + i * 32 + lane;
        v[i] = __bfloat162float(zhh[o]) + __bfloat162float(zhl[o]);
        s += v[i];
    }
#pragma unroll
    for (int o = 16; o; o >>= 1) s += __shfl_xor_sync(0xffffffffu, s, o);
    float mu = s * (1.0f / 256.0f);
    float q = 0.0f;
#pragma unroll
    for (int i = 0; i < 8; i++) { float d = v[i] - mu; q += d * d; }
#pragma unroll
    for (int o = 16; o; o >>= 1) q += __shfl_xor_sync(0xffffffffu, q, o);
    float rstd = rsqrtf(q * (1.0f / 256.0f) + 1e-5f);
    float d0 = 0.0f, d1 = 0.0f;
#pragma unroll
    for (int i = 0; i < 8; i++) {
        int j = i * 32 + lane;
        float nm = (v[i] - mu) * rstd * ln_g[j] + ln_b[j];
        d0 += nm * ow[j];
        d1 += nm * ow[256 + j];
    }
#pragma unroll
    for (int o = 16; o; o >>= 1) {
        d0 += __shfl_xor_sync(0xffffffffu, d0, o);
        d1 += __shfl_xor_sync(0xffffffffu, d1, o);
    }
    size_t lbase = full ? (size_t)NB * 512 : 0;
    if (lane == 0) {
        out[lbase + 2 * (size_t)b]     = d0 + ob[0];
        out[lbase + 2 * (size_t)b + 1] = d1 + ob[1];
    }
    if (full) {
#pragma unroll
        for (int i = 0; i < 8; i++) {
            int j = i * 32 + lane;
            size_t o = (size_t)b * 256 + j;
            out[o] = v[i];
            out[(size_t)NB * 256 + o] = __bfloat162float(zlh[o]) + __bfloat162float(zll[o]);
        }
    }
}

// ---------------- launch ---------------------------------------------------------
extern "C" void kernel_launch(void* const* d_in, const int* in_sizes, int n_in,
                              void* d_out, int out_size)
{
    const float* x         = (const float*)d_in[0];
    const float* proj_w    = (const float*)d_in[1];
    const float* proj_b    = (const float*)d_in[2];
    const float* low_w_ih  = (const float*)d_in[3];
    const float* low_w_hh  = (const float*)d_in[4];
    const float* low_b_ih  = (const float*)d_in[5];
    const float* low_b_hh  = (const float*)d_in[6];
    const float* high_w_ih = (const float*)d_in[7];
    const float* high_w_hh = (const float*)d_in[8];
    const float* high_b_ih = (const float*)d_in[9];
    const float* high_b_hh = (const float*)d_in[10];
    const float* ln_g      = (const float*)d_in[11];
    const float* ln_b      = (const float*)d_in[12];
    const float* out_w     = (const float*)d_in[13];
    const float* out_b     = (const float*)d_in[14];
    float* out = (float*)d_out;

    bf16 *Xh0, *Xh1, *Xl0, *Xl1, *XEh, *XEl;
    bf16 *ZHh[2], *ZHl[2], *ZLh[2], *ZLl[2];
    bf16 *WLh, *WLl, *WHh, *WHl, *PWh, *PWl;
    float *BL, *BH, *CX, *CXH;
    {
        bf16 *p;
        cudaGetSymbolAddress((void**)&p, g_Xh);  Xh0 = p; Xh1 = p + (size_t)NB*256;
        cudaGetSymbolAddress((void**)&p, g_Xl);  Xl0 = p; Xl1 = p + (size_t)NB*256;
        cudaGetSymbolAddress((void**)&XEh, g_XEh);
        cudaGetSymbolAddress((void**)&XEl, g_XEl);
        cudaGetSymbolAddress((void**)&p, g_ZHh); ZHh[0] = p; ZHh[1] = p + (size_t)NB*256;
        cudaGetSymbolAddress((void**)&p, g_ZHl); ZHl[0] = p; ZHl[1] = p + (size_t)NB*256;
        cudaGetSymbolAddress((void**)&p, g_ZLh); ZLh[0] = p; ZLh[1] = p + (size_t)NB*256;
        cudaGetSymbolAddress((void**)&p, g_ZLl); ZLl[0] = p; ZLl[1] = p + (size_t)NB*256;
        cudaGetSymbolAddress((void**)&WLh, g_WLh);
        cudaGetSymbolAddress((void**)&WLl, g_WLl);
        cudaGetSymbolAddress((void**)&WHh, g_WHh);
        cudaGetSymbolAddress((void**)&WHl, g_WHl);
        cudaGetSymbolAddress((void**)&PWh, g_PWh);
        cudaGetSymbolAddress((void**)&PWl, g_PWl);
        cudaGetSymbolAddress((void**)&BL, g_BL);
        cudaGetSymbolAddress((void**)&BH, g_BH);
        cudaGetSymbolAddress((void**)&CX,  g_CX);
        cudaGetSymbolAddress((void**)&CXH, g_CXH);
    }

    cudaFuncSetAttribute(gemm_fused<0>, cudaFuncAttributeMaxDynamicSharedMemorySize, SMEM_BYTES);
    cudaFuncSetAttribute(gemm_fused<1>, cudaFuncAttributeMaxDynamicSharedMemorySize, SMEM_BYTES);
    cudaFuncSetAttribute(gemm_fused<2>, cudaFuncAttributeMaxDynamicSharedMemorySize, SMEM_BYTES);
    cudaFuncSetAttribute(gemm_fused<3>, cudaFuncAttributeMaxDynamicSharedMemorySize, SMEM_BYTES);

    // prep
    zero_state_k<<<(NB * 256) / 256, 256>>>();
    split_x_k<<<(NB * 512) / 256, 256>>>(x);
    split_generic_k<<<(256 * 512 + 255) / 256, 256>>>(proj_w, PWh, PWl, 256 * 512);
    prep_low_w <<<(1024 * 768) / 256, 256>>>(low_w_ih, low_w_hh);
    prep_high_w<<<(1024 * 512) / 256, 256>>>(high_w_ih, high_w_hh);
    prep_bias_k<<<4, 256>>>(low_b_ih,  low_b_hh,  BL);
    prep_bias_k<<<4, 256>>>(high_b_ih, high_b_hh, BH);

    const dim3 gN4(4, NB / 128);

    // x_embed = GELU(x @ proj_w^T + b) -> XE hi/lo
    gemm_fused<1><<<dim3(1, NB / 128), 256, SMEM_BYTES>>>(
        Xh0, Xh1, Xl0, Xl1, PWh, PWl, 512, 512, proj_b, nullptr,
        nullptr, nullptr, XEh, XEl, nullptr);

    // CX = x_embed @ WL[:,0:256]^T + BL  (constant across all low steps)
    gemm_fused<2><<<gN4, 256, SMEM_BYTES>>>(
        XEh, XEh, XEl, XEl, WLh, WLl, 768, 256, BL, nullptr,
        nullptr, nullptr, nullptr, nullptr, CX);

    int zh = 0, zl = 0;
    const float* base = CX;   // z_h = 0 during the first cycle
    for (int i = 0; i < 12; i++) {
        // low GRU step: only the z_l K-slice, cached base added in epilogue
        gemm_fused<0><<<gN4, 256, SMEM_BYTES>>>(
            ZLh[zl], ZLh[zl], ZLl[zl], ZLl[zl], WLh + 512, WLl + 512, 768, 256,
            BL, base, ZLh[zl], ZLl[zl], ZLh[zl ^ 1], ZLl[zl ^ 1], nullptr);
        zl ^= 1;

        if ((i + 1) % 4 == 0) {
            // high GRU step: full K=512 over [z_l | z_h]
            gemm_fused<0><<<gN4, 256, SMEM_BYTES>>>(
                ZLh[zl], ZHh[zh], ZLl[zl], ZHl[zh], WHh, WHl, 512, 512,
                BH, nullptr, ZHh[zh], ZHl[zh], ZHh[zh ^ 1], ZHl[zh ^ 1], nullptr);
            zh ^= 1;

            if (i < 11) {
                // refresh cached base: CXH = CX + z_h @ WL[:,256:512]^T
                gemm_fused<3><<<gN4, 256, SMEM_BYTES>>>(
                    ZHh[zh], ZHh[zh], ZHl[zh], ZHl[zh], WLh + 256, WLl + 256, 768, 256,
                    nullptr, CX, nullptr, nullptr, nullptr, nullptr, CXH);
                base = CXH;
            }
        }
    }

    int full = (out_size >= NB * 514) ? 1 : 0;
    head_k<<<NB / 8, 256>>>(ZHh[zh], ZHl[zh], ZLh[zl], ZLl[zl],
                            ln_g, ln_b, out_w, out_b, out, full);
}